// round 1
// baseline (speedup 1.0000x reference)
#include <cuda_runtime.h>
#include <math.h>

#define NN 100000
#define NE 1600000
#define NV 15000
#define DD 128
#define NG 16

// ---------------- device scratch (static: no allocations allowed) ------------
__device__ int   g_off[NN + 1];      // degree -> exclusive offsets (in place)
__device__ int   g_cursor[NN];       // scatter cursors
__device__ int2  g_ma[NE];           // {word_ids[src], bits(w*norm[src])} for layer-1 agg
__device__ int2  g_mb[NE];           // {src,           bits(w*norm[src])} for layer-2 agg
__device__ float g_P [NV * DD];      // embeds @ W0   (vocab-level, L2-resident)
__device__ float g_H0[NN * DD];      // layer-1 output
__device__ float g_S1[NN * DD];      // N*A*N*H0 (pre-GEMM layer-2)
__device__ float g_pool[NG * DD];    // per-graph max (relu>=0, int-compare safe)

// ---------------- small helpers ---------------------------------------------
__device__ __forceinline__ unsigned long long dup2(float x) {
    unsigned long long r;
    asm("mov.b64 %0, {%1, %1};" : "=l"(r) : "f"(x));
    return r;
}
__device__ __forceinline__ unsigned long long ffma2(unsigned long long a,
                                                    unsigned long long b,
                                                    unsigned long long c) {
    unsigned long long d;
    asm("fma.rn.f32x2 %0, %1, %2, %3;" : "=l"(d) : "l"(a), "l"(b), "l"(c));
    return d;
}
__device__ __forceinline__ float2 unpk(unsigned long long v) {
    float2 r;
    asm("mov.b64 {%0, %1}, %2;" : "=f"(r.x), "=f"(r.y) : "l"(v));
    return r;
}

// ---------------- CSR build --------------------------------------------------
__global__ void k_zero() {
    int i = blockIdx.x * 256 + threadIdx.x;
    if (i <= NN) g_off[i] = 0;
    if (i < NG * DD) g_pool[i] = 0.0f;
}

__global__ void k_hist(const int* __restrict__ edst) {
    int e = blockIdx.x * 256 + threadIdx.x;
    if (e < NE) atomicAdd(&g_off[edst[e]], 1);
}

__global__ void k_scan() {
    __shared__ int part[1024];
    int t = threadIdx.x;
    const int CH = (NN + 1023) / 1024;     // 98
    int s0 = t * CH;
    int s1 = s0 + CH; if (s1 > NN) s1 = NN;
    int s = 0;
    for (int i = s0; i < s1; i++) s += g_off[i];
    part[t] = s;
    __syncthreads();
    for (int off = 1; off < 1024; off <<= 1) {
        int v = (t >= off) ? part[t - off] : 0;
        __syncthreads();
        part[t] += v;
        __syncthreads();
    }
    int run = part[t] - s;                 // exclusive prefix
    for (int i = s0; i < s1; i++) {
        int d = g_off[i];
        g_off[i] = run;
        g_cursor[i] = run;
        run += d;
    }
    if (t == 1023) g_off[NN] = part[1023];
}

__global__ void k_scatter(const int* __restrict__ esrc, const int* __restrict__ edst,
                          const float* __restrict__ ew, const float* __restrict__ norm,
                          const int* __restrict__ word_ids) {
    int e = blockIdx.x * 256 + threadIdx.x;
    if (e >= NE) return;
    int d = edst[e];
    int s = esrc[e];
    int pos = atomicAdd(&g_cursor[d], 1);
    float wn = ew[e] * __ldg(&norm[s]);
    int wb = __float_as_int(wn);
    g_ma[pos] = make_int2(__ldg(&word_ids[s]), wb);
    g_mb[pos] = make_int2(s, wb);
}

// ---------------- edge aggregation (warp per dst node) -----------------------
// MODE 0: acc = sum wn * P[wid];  H0 = relu(acc*norm[dst] + b0)
// MODE 1: acc = sum wn * H0[src]; S1 = acc*norm[dst]
template <int MODE>
__global__ __launch_bounds__(256) void agg_k(const float* __restrict__ norm,
                                             const float* __restrict__ bias) {
    int node = (blockIdx.x * 256 + threadIdx.x) >> 5;
    if (node >= NN) return;
    int lane = threadIdx.x & 31;
    int beg = g_off[node], end = g_off[node + 1];
    const float4* tbl = (const float4*)((MODE == 0) ? g_P : g_H0);
    const int2* meta = (MODE == 0) ? g_ma : g_mb;

    float ax = 0.f, ay = 0.f, az = 0.f, aw = 0.f;
    int e = beg;
    for (; e + 4 <= end; e += 4) {
        int2 m0 = __ldg(meta + e);
        int2 m1 = __ldg(meta + e + 1);
        int2 m2 = __ldg(meta + e + 2);
        int2 m3 = __ldg(meta + e + 3);
        float4 v0 = __ldg(tbl + m0.x * 32 + lane);
        float4 v1 = __ldg(tbl + m1.x * 32 + lane);
        float4 v2 = __ldg(tbl + m2.x * 32 + lane);
        float4 v3 = __ldg(tbl + m3.x * 32 + lane);
        float c0 = __int_as_float(m0.y), c1 = __int_as_float(m1.y);
        float c2 = __int_as_float(m2.y), c3 = __int_as_float(m3.y);
        ax = fmaf(c0, v0.x, fmaf(c1, v1.x, fmaf(c2, v2.x, fmaf(c3, v3.x, ax))));
        ay = fmaf(c0, v0.y, fmaf(c1, v1.y, fmaf(c2, v2.y, fmaf(c3, v3.y, ay))));
        az = fmaf(c0, v0.z, fmaf(c1, v1.z, fmaf(c2, v2.z, fmaf(c3, v3.z, az))));
        aw = fmaf(c0, v0.w, fmaf(c1, v1.w, fmaf(c2, v2.w, fmaf(c3, v3.w, aw))));
    }
    for (; e < end; e++) {
        int2 m = __ldg(meta + e);
        float4 v = __ldg(tbl + m.x * 32 + lane);
        float c = __int_as_float(m.y);
        ax = fmaf(c, v.x, ax); ay = fmaf(c, v.y, ay);
        az = fmaf(c, v.z, az); aw = fmaf(c, v.w, aw);
    }
    float nd = __ldg(norm + node);
    float4 r = make_float4(ax * nd, ay * nd, az * nd, aw * nd);
    if (MODE == 0) {
        float4 b = __ldg((const float4*)bias + lane);
        r.x = fmaxf(r.x + b.x, 0.f);
        r.y = fmaxf(r.y + b.y, 0.f);
        r.z = fmaxf(r.z + b.z, 0.f);
        r.w = fmaxf(r.w + b.w, 0.f);
        ((float4*)g_H0)[node * 32 + lane] = r;
    } else {
        ((float4*)g_S1)[node * 32 + lane] = r;
    }
}

// ---------------- GEMM (rows x 128) @ W(128x128) via packed f32x2 ------------
// EPI 0: out = A @ W           -> g_P      (A = arg, rows = NV)
// EPI 1: relu(g_S1 @ W + b)    -> max-pool into g_pool (nothing else written)
template <int EPI>
__global__ __launch_bounds__(256, 2) void gemm_k(const float* __restrict__ Aarg,
                                                 const float* __restrict__ W,
                                                 const float* __restrict__ bias,
                                                 const int* __restrict__ gid,
                                                 int nrows) {
    const float* A = (EPI == 0) ? Aarg : g_S1;
    int tx = threadIdx.x & 31;       // 4 output cols: tx*4 .. tx*4+3
    int ty = threadIdx.x >> 5;       // 8 output rows: row0 .. row0+7
    int rb = blockIdx.x * 64;
    int row0 = rb + ty * 8;

    const float4* ap[8];
#pragma unroll
    for (int i = 0; i < 8; i++) {
        int r = row0 + i;
        int rc = (r < nrows) ? r : 0;
        ap[i] = (const float4*)(A + rc * DD);
    }
    const ulonglong2* Wq = (const ulonglong2*)W;

    unsigned long long acc[8][2];
#pragma unroll
    for (int i = 0; i < 8; i++) { acc[i][0] = 0ull; acc[i][1] = 0ull; }

#pragma unroll 2
    for (int k = 0; k < DD; k += 4) {
        float4 a[8];
#pragma unroll
        for (int i = 0; i < 8; i++) a[i] = __ldg(ap[i] + (k >> 2));
#pragma unroll
        for (int kk = 0; kk < 4; kk++) {
            ulonglong2 b = __ldg(Wq + (k + kk) * 32 + tx);
#pragma unroll
            for (int i = 0; i < 8; i++) {
                float av = (kk == 0) ? a[i].x : (kk == 1) ? a[i].y
                         : (kk == 2) ? a[i].z : a[i].w;
                unsigned long long ad = dup2(av);
                acc[i][0] = ffma2(ad, b.x, acc[i][0]);
                acc[i][1] = ffma2(ad, b.y, acc[i][1]);
            }
        }
    }

    if (EPI == 0) {
#pragma unroll
        for (int i = 0; i < 8; i++) {
            int r = row0 + i;
            if (r < nrows) {
                float2 lo = unpk(acc[i][0]);
                float2 hi = unpk(acc[i][1]);
                ((float4*)g_P)[r * 32 + tx] = make_float4(lo.x, lo.y, hi.x, hi.y);
            }
        }
    } else {
        float4 bv = __ldg((const float4*)bias + tx);
        float v[8][4];
#pragma unroll
        for (int i = 0; i < 8; i++) {
            float2 lo = unpk(acc[i][0]);
            float2 hi = unpk(acc[i][1]);
            v[i][0] = fmaxf(lo.x + bv.x, 0.f);
            v[i][1] = fmaxf(lo.y + bv.y, 0.f);
            v[i][2] = fmaxf(hi.x + bv.z, 0.f);
            v[i][3] = fmaxf(hi.y + bv.w, 0.f);
        }
        int gfirst = __ldg(gid + rb);
        int lastrow = rb + 63; if (lastrow >= nrows) lastrow = nrows - 1;
        int glast = __ldg(gid + lastrow);
        __shared__ float sm[8][DD];
        if (gfirst == glast) {
            float m0 = 0.f, m1 = 0.f, m2 = 0.f, m3 = 0.f;
#pragma unroll
            for (int i = 0; i < 8; i++) {
                if (row0 + i < nrows) {
                    m0 = fmaxf(m0, v[i][0]); m1 = fmaxf(m1, v[i][1]);
                    m2 = fmaxf(m2, v[i][2]); m3 = fmaxf(m3, v[i][3]);
                }
            }
            ((float4*)&sm[ty][0])[tx] = make_float4(m0, m1, m2, m3);
            __syncthreads();
            if (ty == 0) {
                float4 mm = ((float4*)&sm[0][0])[tx];
#pragma unroll
                for (int t = 1; t < 8; t++) {
                    float4 q = ((float4*)&sm[t][0])[tx];
                    mm.x = fmaxf(mm.x, q.x); mm.y = fmaxf(mm.y, q.y);
                    mm.z = fmaxf(mm.z, q.z); mm.w = fmaxf(mm.w, q.w);
                }
                int base = gfirst * DD + tx * 4;
                atomicMax((int*)&g_pool[base + 0], __float_as_int(mm.x));
                atomicMax((int*)&g_pool[base + 1], __float_as_int(mm.y));
                atomicMax((int*)&g_pool[base + 2], __float_as_int(mm.z));
                atomicMax((int*)&g_pool[base + 3], __float_as_int(mm.w));
            }
        } else {
            // rare: graph boundary inside this 64-row tile
#pragma unroll
            for (int i = 0; i < 8; i++) {
                int r = row0 + i;
                if (r < nrows) {
                    int gg = __ldg(gid + r);
                    int base = gg * DD + tx * 4;
                    atomicMax((int*)&g_pool[base + 0], __float_as_int(v[i][0]));
                    atomicMax((int*)&g_pool[base + 1], __float_as_int(v[i][1]));
                    atomicMax((int*)&g_pool[base + 2], __float_as_int(v[i][2]));
                    atomicMax((int*)&g_pool[base + 3], __float_as_int(v[i][3]));
                }
            }
        }
    }
}

// ---------------- head: z = g@Wout + bout, BCE loss, sigmoid -----------------
__global__ void k_final(const float* __restrict__ Wout, const float* __restrict__ bout,
                        const float* __restrict__ y, float* __restrict__ out,
                        int out_size) {
    __shared__ float s_loss[NG];
    __shared__ float s_pred[NG];
    int warp = threadIdx.x >> 5;
    int lane = threadIdx.x & 31;
    if (warp < NG) {
        float4 gv = ((const float4*)g_pool)[warp * 32 + lane];
        float4 wv = __ldg((const float4*)Wout + lane);
        float d = gv.x * wv.x + gv.y * wv.y + gv.z * wv.z + gv.w * wv.w;
#pragma unroll
        for (int o = 16; o > 0; o >>= 1) d += __shfl_xor_sync(0xffffffffu, d, o);
        if (lane == 0) {
            float z = d + __ldg(bout);
            float yd = __ldg(y + warp);
            s_loss[warp] = fmaxf(z, 0.f) - z * yd + log1pf(expf(-fabsf(z)));
            s_pred[warp] = 1.f / (1.f + expf(-z));
        }
    }
    __syncthreads();
    if (threadIdx.x == 0) {
        float L = 0.f;
        for (int i = 0; i < NG; i++) L += s_loss[i];
        L *= (1.f / NG);
        if (out_size >= NG + 1) {
            out[0] = L;
            for (int i = 0; i < NG; i++) out[1 + i] = s_pred[i];
            for (int i = NG + 1; i < out_size; i++) out[i] = 0.f;
        } else if (out_size == NG) {
            for (int i = 0; i < NG; i++) out[i] = s_pred[i];
        } else {
            out[0] = L;
        }
    }
}

// ---------------- launch -----------------------------------------------------
extern "C" void kernel_launch(void* const* d_in, const int* in_sizes, int n_in,
                              void* d_out, int out_size) {
    const int*   word_ids = (const int*)d_in[0];
    const int*   esrc     = (const int*)d_in[1];
    const int*   edst     = (const int*)d_in[2];
    const float* ew       = (const float*)d_in[3];
    const float* norm     = (const float*)d_in[4];
    const int*   gid      = (const int*)d_in[5];
    const float* y        = (const float*)d_in[6];
    const float* emb      = (const float*)d_in[7];
    const float* W0       = (const float*)d_in[8];
    const float* b0       = (const float*)d_in[9];
    const float* W1       = (const float*)d_in[10];
    const float* b1       = (const float*)d_in[11];
    const float* Wout     = (const float*)d_in[12];
    const float* bout     = (const float*)d_in[13];
    float* out = (float*)d_out;

    k_zero<<<(NN + 256) / 256, 256>>>();
    k_hist<<<(NE + 255) / 256, 256>>>(edst);
    k_scan<<<1, 1024>>>();
    k_scatter<<<(NE + 255) / 256, 256>>>(esrc, edst, ew, norm, word_ids);

    // layer 1: P = embeds @ W0 (vocab-level), then agg+bias+relu -> H0
    gemm_k<0><<<(NV + 63) / 64, 256>>>(emb, W0, nullptr, nullptr, NV);
    agg_k<0><<<(NN + 7) / 8, 256>>>(norm, b0);

    // layer 2: S1 = N*A*N*H0, then relu(S1@W1+b1) fused with max-pool
    agg_k<1><<<(NN + 7) / 8, 256>>>(norm, nullptr);
    gemm_k<1><<<(NN + 63) / 64, 256>>>(nullptr, W1, b1, gid, NN);

    k_final<<<1, 512>>>(Wout, bout, y, out, out_size);
}

// round 2
// speedup vs baseline: 1.1165x; 1.1165x over previous
#include <cuda_runtime.h>
#include <cuda_fp16.h>
#include <math.h>

#define NN 100000
#define NE 1600000
#define NV 15000
#define DD 128
#define NG 16

// ---------------- device scratch (static: no allocations allowed) ------------
__device__ int    g_off[NN + 1];      // degree -> exclusive offsets (in place)
__device__ int    g_cursor[NN];       // scatter cursors
__device__ int2   g_meta[NE];         // {src, bits(w*norm[src])}  (single meta array)
__device__ __half g_Ph[NV * DD];      // embeds @ W0  in fp16 (3.8 MB, L2-resident)
__device__ __half g_H0h[NN * DD];     // layer-1 output in fp16 (25.6 MB, L2-resident)
__device__ float  g_S1[NN * DD];      // N*A*N*H0 (pre-GEMM layer-2, fp32)
__device__ float  g_pool[NG * DD];    // per-graph max (relu>=0, int-compare safe)

// ---------------- small helpers ---------------------------------------------
__device__ __forceinline__ unsigned long long dup2(float x) {
    unsigned long long r;
    asm("mov.b64 %0, {%1, %1};" : "=l"(r) : "f"(x));
    return r;
}
__device__ __forceinline__ unsigned long long ffma2(unsigned long long a,
                                                    unsigned long long b,
                                                    unsigned long long c) {
    unsigned long long d;
    asm("fma.rn.f32x2 %0, %1, %2, %3;" : "=l"(d) : "l"(a), "l"(b), "l"(c));
    return d;
}
__device__ __forceinline__ float2 unpk(unsigned long long v) {
    float2 r;
    asm("mov.b64 {%0, %1}, %2;" : "=f"(r.x), "=f"(r.y) : "l"(v));
    return r;
}
__device__ __forceinline__ void split_h2(float2 raw, float2& f0, float2& f1) {
    __half2 h0 = *reinterpret_cast<__half2*>(&raw.x);
    __half2 h1 = *reinterpret_cast<__half2*>(&raw.y);
    f0 = __half22float2(h0);
    f1 = __half22float2(h1);
}

// ---------------- CSR build --------------------------------------------------
__global__ void k_zero() {
    int i = blockIdx.x * 256 + threadIdx.x;
    if (i <= NN) g_off[i] = 0;
    if (i < NG * DD) g_pool[i] = 0.0f;
}

__global__ void k_hist(const int* __restrict__ edst) {
    int e = blockIdx.x * 256 + threadIdx.x;
    if (e < NE) atomicAdd(&g_off[edst[e]], 1);
}

__global__ void k_scan() {
    __shared__ int part[1024];
    int t = threadIdx.x;
    const int CH = (NN + 1023) / 1024;     // 98
    int s0 = t * CH;
    int s1 = s0 + CH; if (s1 > NN) s1 = NN;
    int s = 0;
    for (int i = s0; i < s1; i++) s += g_off[i];
    part[t] = s;
    __syncthreads();
    for (int off = 1; off < 1024; off <<= 1) {
        int v = (t >= off) ? part[t - off] : 0;
        __syncthreads();
        part[t] += v;
        __syncthreads();
    }
    int run = part[t] - s;                 // exclusive prefix
    for (int i = s0; i < s1; i++) {
        int d = g_off[i];
        g_off[i] = run;
        g_cursor[i] = run;
        run += d;
    }
    if (t == 1023) g_off[NN] = part[1023];
}

__global__ void k_scatter(const int* __restrict__ esrc, const int* __restrict__ edst,
                          const float* __restrict__ ew, const float* __restrict__ norm) {
    int e = blockIdx.x * 256 + threadIdx.x;
    if (e >= NE) return;
    int d = edst[e];
    int s = esrc[e];
    int pos = atomicAdd(&g_cursor[d], 1);
    float wn = ew[e] * __ldg(&norm[s]);
    g_meta[pos] = make_int2(s, __float_as_int(wn));
}

// ---------------- edge aggregation (warp per dst node) -----------------------
// MODE 0: acc = sum wn * Ph[word_ids[src]]; H0h = half(relu(acc*norm[dst] + b0))
// MODE 1: acc = sum wn * H0h[src];          S1  = acc*norm[dst]
template <int MODE>
__global__ __launch_bounds__(256) void agg_k(const float* __restrict__ norm,
                                             const float* __restrict__ bias,
                                             const int* __restrict__ word_ids) {
    int node = (blockIdx.x * 256 + threadIdx.x) >> 5;
    if (node >= NN) return;
    int lane = threadIdx.x & 31;
    int beg = g_off[node], end = g_off[node + 1];
    const float2* tbl = (const float2*)((MODE == 0) ? g_Ph : g_H0h);  // 32 chunks/row

    float ax = 0.f, ay = 0.f, az = 0.f, aw = 0.f;
    int e = beg;
    for (; e + 8 <= end; e += 8) {
        int2 m[8];
#pragma unroll
        for (int j = 0; j < 8; j++) m[j] = __ldg(g_meta + e + j);
        int idx[8];
#pragma unroll
        for (int j = 0; j < 8; j++)
            idx[j] = (MODE == 0) ? __ldg(word_ids + m[j].x) : m[j].x;
        float2 raw[8];
#pragma unroll
        for (int j = 0; j < 8; j++) raw[j] = __ldg(tbl + idx[j] * 32 + lane);
#pragma unroll
        for (int j = 0; j < 8; j++) {
            float c = __int_as_float(m[j].y);
            float2 f0, f1; split_h2(raw[j], f0, f1);
            ax = fmaf(c, f0.x, ax); ay = fmaf(c, f0.y, ay);
            az = fmaf(c, f1.x, az); aw = fmaf(c, f1.y, aw);
        }
    }
    for (; e < end; e++) {
        int2 m = __ldg(g_meta + e);
        int idx = (MODE == 0) ? __ldg(word_ids + m.x) : m.x;
        float2 raw = __ldg(tbl + idx * 32 + lane);
        float c = __int_as_float(m.y);
        float2 f0, f1; split_h2(raw, f0, f1);
        ax = fmaf(c, f0.x, ax); ay = fmaf(c, f0.y, ay);
        az = fmaf(c, f1.x, az); aw = fmaf(c, f1.y, aw);
    }
    float nd = __ldg(norm + node);
    if (MODE == 0) {
        float4 b = __ldg((const float4*)bias + lane);
        float rx = fmaxf(fmaf(ax, nd, b.x), 0.f);
        float ry = fmaxf(fmaf(ay, nd, b.y), 0.f);
        float rz = fmaxf(fmaf(az, nd, b.z), 0.f);
        float rw = fmaxf(fmaf(aw, nd, b.w), 0.f);
        __half2 h0 = __floats2half2_rn(rx, ry);
        __half2 h1 = __floats2half2_rn(rz, rw);
        float2 outp;
        *reinterpret_cast<__half2*>(&outp.x) = h0;
        *reinterpret_cast<__half2*>(&outp.y) = h1;
        ((float2*)g_H0h)[node * 32 + lane] = outp;
    } else {
        ((float4*)g_S1)[node * 32 + lane] =
            make_float4(ax * nd, ay * nd, az * nd, aw * nd);
    }
}

// ---------------- GEMM (rows x 128) @ W(128x128) via packed f32x2 ------------
// EPI 0: Ph = half(A @ W)                    (A = arg fp32, rows = NV)
// EPI 1: relu(g_S1 @ W + b) -> max-pool into g_pool (H1 never materialized)
template <int EPI>
__global__ __launch_bounds__(256, 2) void gemm_k(const float* __restrict__ Aarg,
                                                 const float* __restrict__ W,
                                                 const float* __restrict__ bias,
                                                 const int* __restrict__ gid,
                                                 int nrows) {
    const float* A = (EPI == 0) ? Aarg : g_S1;
    int tx = threadIdx.x & 31;       // 4 output cols: tx*4 .. tx*4+3
    int ty = threadIdx.x >> 5;       // 8 output rows: row0 .. row0+7
    int rb = blockIdx.x * 64;
    int row0 = rb + ty * 8;

    const float4* ap[8];
#pragma unroll
    for (int i = 0; i < 8; i++) {
        int r = row0 + i;
        int rc = (r < nrows) ? r : 0;
        ap[i] = (const float4*)(A + rc * DD);
    }
    const ulonglong2* Wq = (const ulonglong2*)W;

    unsigned long long acc[8][2];
#pragma unroll
    for (int i = 0; i < 8; i++) { acc[i][0] = 0ull; acc[i][1] = 0ull; }

#pragma unroll 2
    for (int k = 0; k < DD; k += 4) {
        float4 a[8];
#pragma unroll
        for (int i = 0; i < 8; i++) a[i] = __ldg(ap[i] + (k >> 2));
#pragma unroll
        for (int kk = 0; kk < 4; kk++) {
            ulonglong2 b = __ldg(Wq + (k + kk) * 32 + tx);
#pragma unroll
            for (int i = 0; i < 8; i++) {
                float av = (kk == 0) ? a[i].x : (kk == 1) ? a[i].y
                         : (kk == 2) ? a[i].z : a[i].w;
                unsigned long long ad = dup2(av);
                acc[i][0] = ffma2(ad, b.x, acc[i][0]);
                acc[i][1] = ffma2(ad, b.y, acc[i][1]);
            }
        }
    }

    if (EPI == 0) {
#pragma unroll
        for (int i = 0; i < 8; i++) {
            int r = row0 + i;
            if (r < nrows) {
                float2 lo = unpk(acc[i][0]);
                float2 hi = unpk(acc[i][1]);
                __half2 h0 = __floats2half2_rn(lo.x, lo.y);
                __half2 h1 = __floats2half2_rn(hi.x, hi.y);
                float2 outp;
                *reinterpret_cast<__half2*>(&outp.x) = h0;
                *reinterpret_cast<__half2*>(&outp.y) = h1;
                ((float2*)g_Ph)[r * 32 + tx] = outp;
            }
        }
    } else {
        float4 bv = __ldg((const float4*)bias + tx);
        float v[8][4];
#pragma unroll
        for (int i = 0; i < 8; i++) {
            float2 lo = unpk(acc[i][0]);
            float2 hi = unpk(acc[i][1]);
            v[i][0] = fmaxf(lo.x + bv.x, 0.f);
            v[i][1] = fmaxf(lo.y + bv.y, 0.f);
            v[i][2] = fmaxf(hi.x + bv.z, 0.f);
            v[i][3] = fmaxf(hi.y + bv.w, 0.f);
        }
        int gfirst = __ldg(gid + rb);
        int lastrow = rb + 63; if (lastrow >= nrows) lastrow = nrows - 1;
        int glast = __ldg(gid + lastrow);
        __shared__ float sm[8][DD];
        if (gfirst == glast) {
            float m0 = 0.f, m1 = 0.f, m2 = 0.f, m3 = 0.f;
#pragma unroll
            for (int i = 0; i < 8; i++) {
                if (row0 + i < nrows) {
                    m0 = fmaxf(m0, v[i][0]); m1 = fmaxf(m1, v[i][1]);
                    m2 = fmaxf(m2, v[i][2]); m3 = fmaxf(m3, v[i][3]);
                }
            }
            ((float4*)&sm[ty][0])[tx] = make_float4(m0, m1, m2, m3);
            __syncthreads();
            if (ty == 0) {
                float4 mm = ((float4*)&sm[0][0])[tx];
#pragma unroll
                for (int t = 1; t < 8; t++) {
                    float4 q = ((float4*)&sm[t][0])[tx];
                    mm.x = fmaxf(mm.x, q.x); mm.y = fmaxf(mm.y, q.y);
                    mm.z = fmaxf(mm.z, q.z); mm.w = fmaxf(mm.w, q.w);
                }
                int base = gfirst * DD + tx * 4;
                atomicMax((int*)&g_pool[base + 0], __float_as_int(mm.x));
                atomicMax((int*)&g_pool[base + 1], __float_as_int(mm.y));
                atomicMax((int*)&g_pool[base + 2], __float_as_int(mm.z));
                atomicMax((int*)&g_pool[base + 3], __float_as_int(mm.w));
            }
        } else {
            // rare: graph boundary inside this 64-row tile
#pragma unroll
            for (int i = 0; i < 8; i++) {
                int r = row0 + i;
                if (r < nrows) {
                    int gg = __ldg(gid + r);
                    int base = gg * DD + tx * 4;
                    atomicMax((int*)&g_pool[base + 0], __float_as_int(v[i][0]));
                    atomicMax((int*)&g_pool[base + 1], __float_as_int(v[i][1]));
                    atomicMax((int*)&g_pool[base + 2], __float_as_int(v[i][2]));
                    atomicMax((int*)&g_pool[base + 3], __float_as_int(v[i][3]));
                }
            }
        }
    }
}

// ---------------- head: z = g@Wout + bout, BCE loss, sigmoid -----------------
__global__ void k_final(const float* __restrict__ Wout, const float* __restrict__ bout,
                        const float* __restrict__ y, float* __restrict__ out,
                        int out_size) {
    __shared__ float s_loss[NG];
    __shared__ float s_pred[NG];
    int warp = threadIdx.x >> 5;
    int lane = threadIdx.x & 31;
    if (warp < NG) {
        float4 gv = ((const float4*)g_pool)[warp * 32 + lane];
        float4 wv = __ldg((const float4*)Wout + lane);
        float d = gv.x * wv.x + gv.y * wv.y + gv.z * wv.z + gv.w * wv.w;
#pragma unroll
        for (int o = 16; o > 0; o >>= 1) d += __shfl_xor_sync(0xffffffffu, d, o);
        if (lane == 0) {
            float z = d + __ldg(bout);
            float yd = __ldg(y + warp);
            s_loss[warp] = fmaxf(z, 0.f) - z * yd + log1pf(expf(-fabsf(z)));
            s_pred[warp] = 1.f / (1.f + expf(-z));
        }
    }
    __syncthreads();
    if (threadIdx.x == 0) {
        float L = 0.f;
        for (int i = 0; i < NG; i++) L += s_loss[i];
        L *= (1.f / NG);
        if (out_size >= NG + 1) {
            out[0] = L;
            for (int i = 0; i < NG; i++) out[1 + i] = s_pred[i];
            for (int i = NG + 1; i < out_size; i++) out[i] = 0.f;
        } else if (out_size == NG) {
            for (int i = 0; i < NG; i++) out[i] = s_pred[i];
        } else {
            out[0] = L;
        }
    }
}

// ---------------- launch -----------------------------------------------------
extern "C" void kernel_launch(void* const* d_in, const int* in_sizes, int n_in,
                              void* d_out, int out_size) {
    const int*   word_ids = (const int*)d_in[0];
    const int*   esrc     = (const int*)d_in[1];
    const int*   edst     = (const int*)d_in[2];
    const float* ew       = (const float*)d_in[3];
    const float* norm     = (const float*)d_in[4];
    const int*   gid      = (const int*)d_in[5];
    const float* y        = (const float*)d_in[6];
    const float* emb      = (const float*)d_in[7];
    const float* W0       = (const float*)d_in[8];
    const float* b0       = (const float*)d_in[9];
    const float* W1       = (const float*)d_in[10];
    const float* b1       = (const float*)d_in[11];
    const float* Wout     = (const float*)d_in[12];
    const float* bout     = (const float*)d_in[13];
    float* out = (float*)d_out;

    k_zero<<<(NN + 256) / 256, 256>>>();
    k_hist<<<(NE + 255) / 256, 256>>>(edst);
    k_scan<<<1, 1024>>>();
    k_scatter<<<(NE + 255) / 256, 256>>>(esrc, edst, ew, norm);

    // layer 1: Ph = half(embeds @ W0) (vocab-level), then agg+bias+relu -> H0h
    gemm_k<0><<<(NV + 63) / 64, 256>>>(emb, W0, nullptr, nullptr, NV);
    agg_k<0><<<(NN + 7) / 8, 256>>>(norm, b0, word_ids);

    // layer 2: S1 = N*A*N*H0, then relu(S1@W1+b1) fused with max-pool
    agg_k<1><<<(NN + 7) / 8, 256>>>(norm, nullptr, nullptr);
    gemm_k<1><<<(NN + 63) / 64, 256>>>(nullptr, W1, b1, gid, NN);

    k_final<<<1, 512>>>(Wout, bout, y, out, out_size);
}

// round 3
// speedup vs baseline: 1.1765x; 1.0537x over previous
#include <cuda_runtime.h>
#include <cuda_fp16.h>
#include <mma.h>
#include <math.h>

using namespace nvcuda;

#define NN 100000
#define NE 1600000
#define NV 15000
#define DD 128
#define NG 16

// ---------------- device scratch (static: no allocations allowed) ------------
__device__ int    g_off[NN + 1];
__device__ int    g_cursor[NN];
__device__ int2   g_meta[NE];              // {src, bits(w*norm[src])}
__device__ __half g_Ph[NV * DD];           // embeds @ W0 in fp16 (L2-resident)
__device__ __half g_H0h[NN * DD];          // layer-1 output fp16 (25.6 MB)
__device__ __half g_S1h[(NN + 64) * DD];   // N*A*N*H0 fp16 (padded for TC tiles)
__device__ __half g_embh[(NV + 64) * DD];  // emb fp16 (padded)
__device__ __half g_W0h[DD * DD];
__device__ __half g_W1h[DD * DD];
__device__ float  g_pool[NG * DD];         // per-graph max (relu>=0 -> int cmp ok)

// ---------------- helpers ----------------------------------------------------
__device__ __forceinline__ void split_h2(float2 raw, float2& f0, float2& f1) {
    __half2 h0 = *reinterpret_cast<__half2*>(&raw.x);
    __half2 h1 = *reinterpret_cast<__half2*>(&raw.y);
    f0 = __half22float2(h0);
    f1 = __half22float2(h1);
}

// ---------------- CSR build --------------------------------------------------
__global__ void k_zero() {
    int i = blockIdx.x * 256 + threadIdx.x;
    if (i <= NN) g_off[i] = 0;
    if (i < NG * DD) g_pool[i] = 0.0f;
}

__global__ void k_hist(const int* __restrict__ edst) {
    int e = blockIdx.x * 256 + threadIdx.x;
    if (e < NE) atomicAdd(&g_off[edst[e]], 1);
}

__global__ void k_scan() {
    __shared__ int part[1024];
    int t = threadIdx.x;
    const int CH = (NN + 1023) / 1024;
    int s0 = t * CH;
    int s1 = s0 + CH; if (s1 > NN) s1 = NN;
    int s = 0;
    for (int i = s0; i < s1; i++) s += g_off[i];
    part[t] = s;
    __syncthreads();
    for (int off = 1; off < 1024; off <<= 1) {
        int v = (t >= off) ? part[t - off] : 0;
        __syncthreads();
        part[t] += v;
        __syncthreads();
    }
    int run = part[t] - s;
    for (int i = s0; i < s1; i++) {
        int d = g_off[i];
        g_off[i] = run;
        g_cursor[i] = run;
        run += d;
    }
    if (t == 1023) g_off[NN] = part[1023];
}

__global__ void k_scatter(const int* __restrict__ esrc, const int* __restrict__ edst,
                          const float* __restrict__ ew, const float* __restrict__ norm) {
    int e = blockIdx.x * 256 + threadIdx.x;
    if (e >= NE) return;
    int d = edst[e];
    int s = esrc[e];
    int pos = atomicAdd(&g_cursor[d], 1);
    float wn = ew[e] * __ldg(&norm[s]);
    g_meta[pos] = make_int2(s, __float_as_int(wn));
}

// ---------------- fp32 -> fp16 conversions -----------------------------------
__global__ void k_cvt(const float* __restrict__ emb, const float* __restrict__ W0,
                      const float* __restrict__ W1) {
    int i = blockIdx.x * 256 + threadIdx.x;
    if (i < NV * DD) g_embh[i] = __float2half(emb[i]);
    if (i < DD * DD) {
        g_W0h[i] = __float2half(W0[i]);
        g_W1h[i] = __float2half(W1[i]);
    }
}

// ---------------- edge aggregation (warp per dst node) -----------------------
// MODE 0: acc = sum wn * Ph[word_ids[src]]; H0h = half(relu(acc*norm[dst] + b0))
// MODE 1: acc = sum wn * H0h[src];          S1h = half(acc*norm[dst])
template <int MODE>
__global__ __launch_bounds__(256) void agg_k(const float* __restrict__ norm,
                                             const float* __restrict__ bias,
                                             const int* __restrict__ word_ids) {
    int node = (blockIdx.x * 256 + threadIdx.x) >> 5;
    if (node >= NN) return;
    int lane = threadIdx.x & 31;
    int beg = g_off[node], end = g_off[node + 1];
    const float2* tbl = (const float2*)((MODE == 0) ? g_Ph : g_H0h);

    float ax = 0.f, ay = 0.f, az = 0.f, aw = 0.f;
    int e = beg;
    for (; e + 8 <= end; e += 8) {
        int2 m[8];
#pragma unroll
        for (int j = 0; j < 8; j++) m[j] = __ldg(g_meta + e + j);
        int idx[8];
#pragma unroll
        for (int j = 0; j < 8; j++)
            idx[j] = (MODE == 0) ? __ldg(word_ids + m[j].x) : m[j].x;
        float2 raw[8];
#pragma unroll
        for (int j = 0; j < 8; j++) raw[j] = __ldg(tbl + idx[j] * 32 + lane);
#pragma unroll
        for (int j = 0; j < 8; j++) {
            float c = __int_as_float(m[j].y);
            float2 f0, f1; split_h2(raw[j], f0, f1);
            ax = fmaf(c, f0.x, ax); ay = fmaf(c, f0.y, ay);
            az = fmaf(c, f1.x, az); aw = fmaf(c, f1.y, aw);
        }
    }
    for (; e < end; e++) {
        int2 m = __ldg(g_meta + e);
        int idx = (MODE == 0) ? __ldg(word_ids + m.x) : m.x;
        float2 raw = __ldg(tbl + idx * 32 + lane);
        float c = __int_as_float(m.y);
        float2 f0, f1; split_h2(raw, f0, f1);
        ax = fmaf(c, f0.x, ax); ay = fmaf(c, f0.y, ay);
        az = fmaf(c, f1.x, az); aw = fmaf(c, f1.y, aw);
    }
    float nd = __ldg(norm + node);
    float2 outp;
    if (MODE == 0) {
        float4 b = __ldg((const float4*)bias + lane);
        float rx = fmaxf(fmaf(ax, nd, b.x), 0.f);
        float ry = fmaxf(fmaf(ay, nd, b.y), 0.f);
        float rz = fmaxf(fmaf(az, nd, b.z), 0.f);
        float rw = fmaxf(fmaf(aw, nd, b.w), 0.f);
        *reinterpret_cast<__half2*>(&outp.x) = __floats2half2_rn(rx, ry);
        *reinterpret_cast<__half2*>(&outp.y) = __floats2half2_rn(rz, rw);
        ((float2*)g_H0h)[node * 32 + lane] = outp;
    } else {
        *reinterpret_cast<__half2*>(&outp.x) = __floats2half2_rn(ax * nd, ay * nd);
        *reinterpret_cast<__half2*>(&outp.y) = __floats2half2_rn(az * nd, aw * nd);
        ((float2*)g_S1h)[node * 32 + lane] = outp;
    }
}

// ---------------- tensor-core GEMM (rows x 128) @ (128 x 128) ----------------
// 4 warps/block, each warp 16 rows x 128 cols via wmma 16x16x16 (fp16 -> fp32).
// EPI 0: Ph = half(A @ W)                 (A = g_embh, rows = NV)
// EPI 1: relu(A @ W + b) -> max-pool into g_pool   (A = g_S1h, rows = NN)
template <int EPI>
__global__ __launch_bounds__(128) void gemm_tc(const __half* __restrict__ A,
                                               const __half* __restrict__ Bh,
                                               const float* __restrict__ bias,
                                               const int* __restrict__ gid,
                                               int nrows) {
    __shared__ float sm[64][DD];
    int warp = threadIdx.x >> 5;
    int rb = blockIdx.x * 64;
    int row0 = rb + warp * 16;

    wmma::fragment<wmma::accumulator, 16, 16, 16, float> acc[8];
#pragma unroll
    for (int n = 0; n < 8; n++) wmma::fill_fragment(acc[n], 0.0f);

#pragma unroll
    for (int k = 0; k < 8; k++) {
        wmma::fragment<wmma::matrix_a, 16, 16, 16, __half, wmma::row_major> af;
        wmma::load_matrix_sync(af, A + row0 * DD + k * 16, DD);
#pragma unroll
        for (int n = 0; n < 8; n++) {
            wmma::fragment<wmma::matrix_b, 16, 16, 16, __half, wmma::row_major> bf;
            wmma::load_matrix_sync(bf, Bh + (k * 16) * DD + n * 16, DD);
            wmma::mma_sync(acc[n], af, bf, acc[n]);
        }
    }
#pragma unroll
    for (int n = 0; n < 8; n++)
        wmma::store_matrix_sync(&sm[warp * 16][n * 16], acc[n], DD, wmma::mem_row_major);
    __syncthreads();

    int col = threadIdx.x;   // 128 threads -> one column each
    if (EPI == 0) {
        for (int r = 0; r < 64; r++) {
            int row = rb + r;
            if (row < nrows) g_Ph[row * DD + col] = __float2half(sm[r][col]);
        }
    } else {
        float bv = __ldg(bias + col);
        int gfirst = __ldg(gid + rb);
        int lastrow = rb + 63; if (lastrow >= nrows) lastrow = nrows - 1;
        int glast = __ldg(gid + lastrow);
        if (gfirst == glast) {
            float m = 0.0f;
#pragma unroll 4
            for (int r = 0; r < 64; r++) {
                if (rb + r < nrows)
                    m = fmaxf(m, fmaxf(sm[r][col] + bv, 0.0f));
            }
            atomicMax((int*)&g_pool[gfirst * DD + col], __float_as_int(m));
        } else {
            // rare: graph boundary inside this tile
            for (int r = 0; r < 64; r++) {
                int row = rb + r;
                if (row < nrows) {
                    int gg = __ldg(gid + row);
                    float v = fmaxf(sm[r][col] + bv, 0.0f);
                    atomicMax((int*)&g_pool[gg * DD + col], __float_as_int(v));
                }
            }
        }
    }
}

// ---------------- head: z = g@Wout + bout, BCE loss, sigmoid -----------------
__global__ void k_final(const float* __restrict__ Wout, const float* __restrict__ bout,
                        const float* __restrict__ y, float* __restrict__ out,
                        int out_size) {
    __shared__ float s_loss[NG];
    __shared__ float s_pred[NG];
    int warp = threadIdx.x >> 5;
    int lane = threadIdx.x & 31;
    if (warp < NG) {
        float4 gv = ((const float4*)g_pool)[warp * 32 + lane];
        float4 wv = __ldg((const float4*)Wout + lane);
        float d = gv.x * wv.x + gv.y * wv.y + gv.z * wv.z + gv.w * wv.w;
#pragma unroll
        for (int o = 16; o > 0; o >>= 1) d += __shfl_xor_sync(0xffffffffu, d, o);
        if (lane == 0) {
            float z = d + __ldg(bout);
            float yd = __ldg(y + warp);
            s_loss[warp] = fmaxf(z, 0.f) - z * yd + log1pf(expf(-fabsf(z)));
            s_pred[warp] = 1.f / (1.f + expf(-z));
        }
    }
    __syncthreads();
    if (threadIdx.x == 0) {
        float L = 0.f;
        for (int i = 0; i < NG; i++) L += s_loss[i];
        L *= (1.f / NG);
        if (out_size >= NG + 1) {
            out[0] = L;
            for (int i = 0; i < NG; i++) out[1 + i] = s_pred[i];
            for (int i = NG + 1; i < out_size; i++) out[i] = 0.f;
        } else if (out_size == NG) {
            for (int i = 0; i < NG; i++) out[i] = s_pred[i];
        } else {
            out[0] = L;
        }
    }
}

// ---------------- launch -----------------------------------------------------
extern "C" void kernel_launch(void* const* d_in, const int* in_sizes, int n_in,
                              void* d_out, int out_size) {
    const int*   word_ids = (const int*)d_in[0];
    const int*   esrc     = (const int*)d_in[1];
    const int*   edst     = (const int*)d_in[2];
    const float* ew       = (const float*)d_in[3];
    const float* norm     = (const float*)d_in[4];
    const int*   gid      = (const int*)d_in[5];
    const float* y        = (const float*)d_in[6];
    const float* emb      = (const float*)d_in[7];
    const float* b0       = (const float*)d_in[9];
    const float* W1       = (const float*)d_in[10];
    const float* b1       = (const float*)d_in[11];
    const float* Wout     = (const float*)d_in[12];
    const float* bout     = (const float*)d_in[13];
    const float* W0       = (const float*)d_in[8];
    float* out = (float*)d_out;

    k_zero<<<(NN + 256) / 256, 256>>>();
    k_hist<<<(NE + 255) / 256, 256>>>(edst);
    k_scan<<<1, 1024>>>();
    k_scatter<<<(NE + 255) / 256, 256>>>(esrc, edst, ew, norm);
    k_cvt<<<(NV * DD + 255) / 256, 256>>>(emb, W0, W1);

    // layer 1: Ph = half(embh @ W0h) (vocab-level), then agg+bias+relu -> H0h
    __half* embh_p; cudaGetSymbolAddress((void**)&embh_p, g_embh);
    __half* W0h_p;  cudaGetSymbolAddress((void**)&W0h_p, g_W0h);
    __half* W1h_p;  cudaGetSymbolAddress((void**)&W1h_p, g_W1h);
    __half* S1h_p;  cudaGetSymbolAddress((void**)&S1h_p, g_S1h);

    gemm_tc<0><<<(NV + 63) / 64, 128>>>(embh_p, W0h_p, nullptr, nullptr, NV);
    agg_k<0><<<(NN + 7) / 8, 256>>>(norm, b0, word_ids);

    // layer 2: S1h = half(N*A*N*H0), then relu(S1h@W1h+b1) fused with max-pool
    agg_k<1><<<(NN + 7) / 8, 256>>>(norm, nullptr, nullptr);
    gemm_tc<1><<<(NN + 63) / 64, 128>>>(S1h_p, W1h_p, b1, gid, NN);

    k_final<<<1, 512>>>(Wout, bout, y, out, out_size);
}

// round 4
// speedup vs baseline: 1.9439x; 1.6524x over previous
#include <cuda_runtime.h>
#include <cuda_fp16.h>
#include <mma.h>
#include <math.h>

using namespace nvcuda;

#define NN 100000
#define NE 1600000
#define NV 15000
#define DD 128
#define NG 16
#define NPAD 100352                 // 98 * 1024, covers NN for the 3-pass scan
#define NSCB 98                     // scan blocks (1024 elems each)

// ---------------- device scratch (static: no allocations allowed) ------------
__device__ int    g_off[NPAD + 4];         // counts -> exclusive offsets
__device__ int    g_cursor[NPAD + 4];      // scatter cursors
__device__ int    g_bsum[NSCB];            // per-block sums (scan pass 1)
__device__ int    g_boff[NSCB];            // per-block exclusive offsets (pass 2)
__device__ int2   g_meta[NE];              // {(wid<<17)|src, bits(w*norm[src])}
__device__ __half g_Ph[NV * DD];           // embeds @ W0 in fp16 (L2-resident)
__device__ __half g_H0h[NN * DD];          // layer-1 output fp16 (25.6 MB)
__device__ __half g_S1h[(NN + 64) * DD];   // N*A*N*H0 fp16 (padded for TC tiles)
__device__ __half g_embh[(NV + 128) * DD]; // emb fp16 (padded past last TC block)
__device__ __half g_W0h[DD * DD];
__device__ __half g_W1h[DD * DD];
__device__ float  g_pool[NG * DD];         // per-graph max (relu>=0 -> int cmp ok)

// ---------------- helpers ----------------------------------------------------
__device__ __forceinline__ void split_h2(float2 raw, float2& f0, float2& f1) {
    __half2 h0 = *reinterpret_cast<__half2*>(&raw.x);
    __half2 h1 = *reinterpret_cast<__half2*>(&raw.y);
    f0 = __half22float2(h0);
    f1 = __half22float2(h1);
}

// ---------------- CSR build --------------------------------------------------
__global__ void k_zero() {
    int i = blockIdx.x * 256 + threadIdx.x;
    if (i < NPAD + 4) g_off[i] = 0;
    if (i < NG * DD) g_pool[i] = 0.0f;
}

__global__ void k_hist(const int* __restrict__ edst) {
    int e = blockIdx.x * 256 + threadIdx.x;
    if (e < NE) atomicAdd(&g_off[edst[e]], 1);
}

// pass 1: per-1024-chunk sums (coalesced int4)
__global__ void k_scan1() {
    __shared__ int sm[256];
    int b = blockIdx.x, t = threadIdx.x;
    int4 c = ((const int4*)g_off)[b * 256 + t];
    int s = c.x + c.y + c.z + c.w;
    sm[t] = s;
    __syncthreads();
    for (int off = 128; off > 0; off >>= 1) {
        if (t < off) sm[t] += sm[t + off];
        __syncthreads();
    }
    if (t == 0) g_bsum[b] = sm[0];
}

// pass 2: exclusive scan of the 98 block sums (one tiny block)
__global__ void k_scan2() {
    __shared__ int sm[128];
    int t = threadIdx.x;
    int v = (t < NSCB) ? g_bsum[t] : 0;
    sm[t] = v;
    __syncthreads();
    for (int off = 1; off < 128; off <<= 1) {
        int u = (t >= off) ? sm[t - off] : 0;
        __syncthreads();
        sm[t] += u;
        __syncthreads();
    }
    if (t < NSCB) g_boff[t] = sm[t] - v;
}

// pass 3: local exclusive scan per chunk + block offset; writes g_off & g_cursor
__global__ void k_scan3() {
    __shared__ int sm[256];
    int b = blockIdx.x, t = threadIdx.x;
    int4 c = ((const int4*)g_off)[b * 256 + t];
    int s = c.x + c.y + c.z + c.w;
    sm[t] = s;
    __syncthreads();
    for (int off = 1; off < 256; off <<= 1) {
        int u = (t >= off) ? sm[t - off] : 0;
        __syncthreads();
        sm[t] += u;
        __syncthreads();
    }
    int base = g_boff[b] + sm[t] - s;   // exclusive prefix for this int4
    int4 o;
    o.x = base;
    o.y = base + c.x;
    o.z = o.y + c.y;
    o.w = o.z + c.z;
    ((int4*)g_off)[b * 256 + t] = o;
    ((int4*)g_cursor)[b * 256 + t] = o;
}

__global__ void k_scatter(const int* __restrict__ esrc, const int* __restrict__ edst,
                          const float* __restrict__ ew, const float* __restrict__ norm,
                          const int* __restrict__ word_ids) {
    int e = blockIdx.x * 256 + threadIdx.x;
    if (e >= NE) return;
    int d = edst[e];
    int s = esrc[e];
    int pos = atomicAdd(&g_cursor[d], 1);
    float wn = ew[e] * __ldg(&norm[s]);
    int packed = s | (__ldg(&word_ids[s]) << 17);   // src < 2^17, wid < 2^14
    g_meta[pos] = make_int2(packed, __float_as_int(wn));
}

// ---------------- fp32 -> fp16 conversions -----------------------------------
__global__ void k_cvt(const float* __restrict__ emb, const float* __restrict__ W0,
                      const float* __restrict__ W1) {
    int i = blockIdx.x * 256 + threadIdx.x;
    if (i < NV * DD) g_embh[i] = __float2half(emb[i]);
    if (i < DD * DD) {
        g_W0h[i] = __float2half(W0[i]);
        g_W1h[i] = __float2half(W1[i]);
    }
}

// ---------------- edge aggregation (warp per dst node) -----------------------
// MODE 0: acc = sum wn * Ph[wid];  H0h = half(relu(acc*norm[dst] + b0))
// MODE 1: acc = sum wn * H0h[src]; S1h = half(acc*norm[dst])
template <int MODE>
__global__ __launch_bounds__(256) void agg_k(const float* __restrict__ norm,
                                             const float* __restrict__ bias) {
    int node = (blockIdx.x * 256 + threadIdx.x) >> 5;
    if (node >= NN) return;
    int lane = threadIdx.x & 31;
    int beg = g_off[node], end = g_off[node + 1];
    const float2* tbl = (const float2*)((MODE == 0) ? g_Ph : g_H0h);

    float ax = 0.f, ay = 0.f, az = 0.f, aw = 0.f;
    int e = beg;
    for (; e + 8 <= end; e += 8) {
        int2 m[8];
#pragma unroll
        for (int j = 0; j < 8; j++) m[j] = __ldg(g_meta + e + j);
        float2 raw[8];
#pragma unroll
        for (int j = 0; j < 8; j++) {
            int idx = (MODE == 0) ? ((unsigned)m[j].x >> 17) : (m[j].x & 0x1FFFF);
            raw[j] = __ldg(tbl + idx * 32 + lane);
        }
#pragma unroll
        for (int j = 0; j < 8; j++) {
            float c = __int_as_float(m[j].y);
            float2 f0, f1; split_h2(raw[j], f0, f1);
            ax = fmaf(c, f0.x, ax); ay = fmaf(c, f0.y, ay);
            az = fmaf(c, f1.x, az); aw = fmaf(c, f1.y, aw);
        }
    }
    for (; e < end; e++) {
        int2 m = __ldg(g_meta + e);
        int idx = (MODE == 0) ? ((unsigned)m.x >> 17) : (m.x & 0x1FFFF);
        float2 raw = __ldg(tbl + idx * 32 + lane);
        float c = __int_as_float(m.y);
        float2 f0, f1; split_h2(raw, f0, f1);
        ax = fmaf(c, f0.x, ax); ay = fmaf(c, f0.y, ay);
        az = fmaf(c, f1.x, az); aw = fmaf(c, f1.y, aw);
    }
    float nd = __ldg(norm + node);
    float2 outp;
    if (MODE == 0) {
        float4 b = __ldg((const float4*)bias + lane);
        float rx = fmaxf(fmaf(ax, nd, b.x), 0.f);
        float ry = fmaxf(fmaf(ay, nd, b.y), 0.f);
        float rz = fmaxf(fmaf(az, nd, b.z), 0.f);
        float rw = fmaxf(fmaf(aw, nd, b.w), 0.f);
        *reinterpret_cast<__half2*>(&outp.x) = __floats2half2_rn(rx, ry);
        *reinterpret_cast<__half2*>(&outp.y) = __floats2half2_rn(rz, rw);
        ((float2*)g_H0h)[node * 32 + lane] = outp;
    } else {
        *reinterpret_cast<__half2*>(&outp.x) = __floats2half2_rn(ax * nd, ay * nd);
        *reinterpret_cast<__half2*>(&outp.y) = __floats2half2_rn(az * nd, aw * nd);
        ((float2*)g_S1h)[node * 32 + lane] = outp;
    }
}

// ---------------- tensor-core GEMM (rows x 128) @ (128 x 128) ----------------
template <int EPI>
__global__ __launch_bounds__(128) void gemm_tc(const __half* __restrict__ A,
                                               const __half* __restrict__ Bh,
                                               const float* __restrict__ bias,
                                               const int* __restrict__ gid,
                                               int nrows) {
    __shared__ float sm[64][DD];
    int warp = threadIdx.x >> 5;
    int rb = blockIdx.x * 64;
    int row0 = rb + warp * 16;

    wmma::fragment<wmma::accumulator, 16, 16, 16, float> acc[8];
#pragma unroll
    for (int n = 0; n < 8; n++) wmma::fill_fragment(acc[n], 0.0f);

#pragma unroll
    for (int k = 0; k < 8; k++) {
        wmma::fragment<wmma::matrix_a, 16, 16, 16, __half, wmma::row_major> af;
        wmma::load_matrix_sync(af, A + row0 * DD + k * 16, DD);
#pragma unroll
        for (int n = 0; n < 8; n++) {
            wmma::fragment<wmma::matrix_b, 16, 16, 16, __half, wmma::row_major> bf;
            wmma::load_matrix_sync(bf, Bh + (k * 16) * DD + n * 16, DD);
            wmma::mma_sync(acc[n], af, bf, acc[n]);
        }
    }
#pragma unroll
    for (int n = 0; n < 8; n++)
        wmma::store_matrix_sync(&sm[warp * 16][n * 16], acc[n], DD, wmma::mem_row_major);
    __syncthreads();

    int col = threadIdx.x;
    if (EPI == 0) {
        for (int r = 0; r < 64; r++) {
            int row = rb + r;
            if (row < nrows) g_Ph[row * DD + col] = __float2half(sm[r][col]);
        }
    } else {
        float bv = __ldg(bias + col);
        int gfirst = __ldg(gid + rb);
        int lastrow = rb + 63; if (lastrow >= nrows) lastrow = nrows - 1;
        int glast = __ldg(gid + lastrow);
        if (gfirst == glast) {
            float m = 0.0f;
#pragma unroll 4
            for (int r = 0; r < 64; r++) {
                if (rb + r < nrows)
                    m = fmaxf(m, fmaxf(sm[r][col] + bv, 0.0f));
            }
            atomicMax((int*)&g_pool[gfirst * DD + col], __float_as_int(m));
        } else {
            for (int r = 0; r < 64; r++) {
                int row = rb + r;
                if (row < nrows) {
                    int gg = __ldg(gid + row);
                    float v = fmaxf(sm[r][col] + bv, 0.0f);
                    atomicMax((int*)&g_pool[gg * DD + col], __float_as_int(v));
                }
            }
        }
    }
}

// ---------------- head: z = g@Wout + bout, BCE loss, sigmoid -----------------
__global__ void k_final(const float* __restrict__ Wout, const float* __restrict__ bout,
                        const float* __restrict__ y, float* __restrict__ out,
                        int out_size) {
    __shared__ float s_loss[NG];
    __shared__ float s_pred[NG];
    int warp = threadIdx.x >> 5;
    int lane = threadIdx.x & 31;
    if (warp < NG) {
        float4 gv = ((const float4*)g_pool)[warp * 32 + lane];
        float4 wv = __ldg((const float4*)Wout + lane);
        float d = gv.x * wv.x + gv.y * wv.y + gv.z * wv.z + gv.w * wv.w;
#pragma unroll
        for (int o = 16; o > 0; o >>= 1) d += __shfl_xor_sync(0xffffffffu, d, o);
        if (lane == 0) {
            float z = d + __ldg(bout);
            float yd = __ldg(y + warp);
            s_loss[warp] = fmaxf(z, 0.f) - z * yd + log1pf(expf(-fabsf(z)));
            s_pred[warp] = 1.f / (1.f + expf(-z));
        }
    }
    __syncthreads();
    if (threadIdx.x == 0) {
        float L = 0.f;
        for (int i = 0; i < NG; i++) L += s_loss[i];
        L *= (1.f / NG);
        if (out_size >= NG + 1) {
            out[0] = L;
            for (int i = 0; i < NG; i++) out[1 + i] = s_pred[i];
            for (int i = NG + 1; i < out_size; i++) out[i] = 0.f;
        } else if (out_size == NG) {
            for (int i = 0; i < NG; i++) out[i] = s_pred[i];
        } else {
            out[0] = L;
        }
    }
}

// ---------------- launch -----------------------------------------------------
extern "C" void kernel_launch(void* const* d_in, const int* in_sizes, int n_in,
                              void* d_out, int out_size) {
    const int*   word_ids = (const int*)d_in[0];
    const int*   esrc     = (const int*)d_in[1];
    const int*   edst     = (const int*)d_in[2];
    const float* ew       = (const float*)d_in[3];
    const float* norm     = (const float*)d_in[4];
    const int*   gid      = (const int*)d_in[5];
    const float* y        = (const float*)d_in[6];
    const float* emb      = (const float*)d_in[7];
    const float* W0       = (const float*)d_in[8];
    const float* b0       = (const float*)d_in[9];
    const float* W1       = (const float*)d_in[10];
    const float* b1       = (const float*)d_in[11];
    const float* Wout     = (const float*)d_in[12];
    const float* bout     = (const float*)d_in[13];
    float* out = (float*)d_out;

    k_zero<<<(NPAD + 4 + 255) / 256, 256>>>();
    k_hist<<<(NE + 255) / 256, 256>>>(edst);
    k_scan1<<<NSCB, 256>>>();
    k_scan2<<<1, 128>>>();
    k_scan3<<<NSCB, 256>>>();
    k_scatter<<<(NE + 255) / 256, 256>>>(esrc, edst, ew, norm, word_ids);
    k_cvt<<<(NV * DD + 255) / 256, 256>>>(emb, W0, W1);

    __half* embh_p; cudaGetSymbolAddress((void**)&embh_p, g_embh);
    __half* W0h_p;  cudaGetSymbolAddress((void**)&W0h_p, g_W0h);
    __half* W1h_p;  cudaGetSymbolAddress((void**)&W1h_p, g_W1h);
    __half* S1h_p;  cudaGetSymbolAddress((void**)&S1h_p, g_S1h);

    // layer 1: Ph = half(embh @ W0h) (vocab-level), then agg+bias+relu -> H0h
    gemm_tc<0><<<(NV + 63) / 64, 128>>>(embh_p, W0h_p, nullptr, nullptr, NV);
    agg_k<0><<<(NN + 7) / 8, 256>>>(norm, b0);

    // layer 2: S1h = half(N*A*N*H0), then relu(S1h@W1h+b1) fused with max-pool
    agg_k<1><<<(NN + 7) / 8, 256>>>(norm, nullptr);
    gemm_tc<1><<<(NN + 63) / 64, 128>>>(S1h_p, W1h_p, b1, gid, NN);

    k_final<<<1, 512>>>(Wout, bout, y, out, out_size);
}